// round 6
// baseline (speedup 1.0000x reference)
#include <cuda_runtime.h>
#include <cstdint>

#define B_SZ   8192
#define K_DIM  1024
#define V_N    2
#define BT     64      // batch rows per CTA
#define PP     64      // panel width
#define KC     32      // k-chunk
#define NTH    512     // 16 warps = 4 per SMSP
#define NPAN   (K_DIM / PP)
#define UR     (2*BT + 4)   // 132 floats, rows 16B-aligned
#define AR     (PP + 4)     // 68

// -------- packed f32x2 helpers (B300 FFMA2 path, PTX-only) --------
__device__ __forceinline__ unsigned long long pack2(float x) {
    unsigned long long r;
    unsigned int u = __float_as_uint(x);
    asm("mov.b64 %0, {%1, %1};" : "=l"(r) : "r"(u));
    return r;
}
__device__ __forceinline__ unsigned long long ffma2(unsigned long long a,
                                                    unsigned long long b,
                                                    unsigned long long c) {
    unsigned long long d;
    asm("fma.rn.f32x2 %0, %1, %2, %3;" : "=l"(d) : "l"(a), "l"(b), "l"(c));
    return d;
}

// GEMM-phase (double-buffered) and solve-phase smem alias
union SMem {
    struct {
        float u_dup[2][KC][UR];   // u_dup[s][k][2b..2b+1] = u[b]  (33.8 KB)
        float a_s[2][KC][AR];     // a_s[s][k][jj] = A[j0+jj][kb*KC+k] (17.4 KB)
    } g;
    struct {
        float diag[PP][AR];       // diag[i][jj] = A[j0+jj][j0+i], 0 for i>=jj
        float up[BT][AR];         // panel values
    } m;
};

__global__ void __launch_bounds__(NTH, 1)
scm_kernel(const float* __restrict__ z,
           const int*   __restrict__ tgt,
           const int*   __restrict__ vari,
           const float* __restrict__ A,
           const float* __restrict__ means,
           const float* __restrict__ logsc,
           float*       __restrict__ out)
{
    __shared__ __align__(16) SMem sm;

    const int tid = threadIdx.x;
    const int b0  = blockIdx.x * BT;
    const int rg  = tid >> 4;   // 0..31 -> rows 2*rg, 2*rg+1
    const int cg  = tid & 15;   // 0..15 -> cols 4*cg..4*cg+3 (2 f32x2 pairs)

    // ---- per-sample intervention scalar (threads 0..63) ----
    int   t_abs = -(1 << 30);
    float vint  = 0.0f;
    if (tid < BT) {
        const int b = b0 + tid;
        const int t = tgt[b];
        if (t >= 0) {
            const int v   = vari[b];
            const float m = means[t * V_N + v];
            const float s = expf(logsc[t * V_N + v]);
            vint  = fmaf(s, z[(size_t)b * K_DIM + t], m);
            t_abs = t;
        }
    }

    // global-load coordinates for chunk staging (1 float4 of u and a per thread)
    const int lr = tid >> 3;    // 0..63 (row)
    const int lc = tid & 7;     // 0..7  (float4 col group)

    for (int p = 0; p < NPAN; ++p) {
        const int j0 = p * PP;

        // ========== GEMM: acc[r][pp] = sum_{k<j0} u[2rg+r][k]*A[j0+jj][k] =====
        unsigned long long acc[2][2];
        acc[0][0] = acc[0][1] = acc[1][0] = acc[1][1] = 0ULL;

        const int nkb = 2 * p;
        if (nkb > 0) {
            float4 ru, ra;
            // prefetch + stage chunk 0 into buffer 0
            ru = *(const float4*)(out + (size_t)(b0 + lr) * K_DIM + 4 * lc);
            ra = *(const float4*)(A   + (size_t)(j0 + lr) * K_DIM + 4 * lc);
            {
                const float uv[4] = {ru.x, ru.y, ru.z, ru.w};
                const float av[4] = {ra.x, ra.y, ra.z, ra.w};
                #pragma unroll
                for (int j = 0; j < 4; ++j) {
                    *(unsigned long long*)&sm.g.u_dup[0][4*lc + j][2*lr] = pack2(uv[j]);
                    sm.g.a_s[0][4*lc + j][lr] = av[j];
                }
            }
            __syncthreads();

            for (int kb = 0; kb < nkb; ++kb) {
                const bool more = (kb + 1 < nkb);
                if (more) {
                    ru = *(const float4*)(out + (size_t)(b0 + lr) * K_DIM + (kb + 1) * KC + 4 * lc);
                    ra = *(const float4*)(A   + (size_t)(j0 + lr) * K_DIM + (kb + 1) * KC + 4 * lc);
                }
                const int s = kb & 1;
                #pragma unroll 8
                for (int k = 0; k < KC; ++k) {
                    // u: 2 duplicated pairs for rows 2rg, 2rg+1 (broadcast load)
                    const ulonglong2 up2 = *(const ulonglong2*)&sm.g.u_dup[s][k][4 * rg];
                    // a: 2 f32x2 col-pairs
                    const ulonglong2 bp  = *(const ulonglong2*)&sm.g.a_s[s][k][4 * cg];
                    acc[0][0] = ffma2(up2.x, bp.x, acc[0][0]);
                    acc[0][1] = ffma2(up2.x, bp.y, acc[0][1]);
                    acc[1][0] = ffma2(up2.y, bp.x, acc[1][0]);
                    acc[1][1] = ffma2(up2.y, bp.y, acc[1][1]);
                }
                if (more) {
                    const int ns = s ^ 1;
                    const float uv[4] = {ru.x, ru.y, ru.z, ru.w};
                    const float av[4] = {ra.x, ra.y, ra.z, ra.w};
                    #pragma unroll
                    for (int j = 0; j < 4; ++j) {
                        *(unsigned long long*)&sm.g.u_dup[ns][4*lc + j][2*lr] = pack2(uv[j]);
                        sm.g.a_s[ns][4*lc + j][lr] = av[j];
                    }
                }
                __syncthreads();
            }
        }

        // ========== switch to solve-phase smem (aliases GEMM tiles) ==========
        // acc -> up
        #pragma unroll
        for (int i = 0; i < 2; ++i) {
            *(unsigned long long*)&sm.m.up[2*rg + i][4*cg]     = acc[i][0];
            *(unsigned long long*)&sm.m.up[2*rg + i][4*cg + 2] = acc[i][1];
        }
        // diagonal block, transposed + strictly-lower masked
        {
            const int jj  = tid & 63;
            const int ig0 = (tid >> 6) * 8;   // 8 groups x 8 i-values
            const float* src = A + (size_t)(j0 + jj) * K_DIM + j0 + ig0;
            #pragma unroll
            for (int q = 0; q < 2; ++q) {
                const float4 r = *(const float4*)(src + 4 * q);
                const int i = ig0 + 4 * q;
                sm.m.diag[i + 0][jj] = (i + 0 < jj) ? r.x : 0.0f;
                sm.m.diag[i + 1][jj] = (i + 1 < jj) ? r.y : 0.0f;
                sm.m.diag[i + 2][jj] = (i + 2 < jj) ? r.z : 0.0f;
                sm.m.diag[i + 3][jj] = (i + 3 < jj) ? r.w : 0.0f;
            }
        }
        __syncthreads();

        // ======= in-panel sequential micro-solve: thread b owns a sample =====
        if (tid < BT) {
            float ul[PP];
            const float* zp = z + (size_t)(b0 + tid) * K_DIM + j0;
            #pragma unroll
            for (int q = 0; q < 16; ++q) {
                const float4 zq = *(const float4*)(zp + 4 * q);
                const float4 aq = *(const float4*)&sm.m.up[tid][4 * q];
                ul[4*q+0] = aq.x + zq.x;
                ul[4*q+1] = aq.y + zq.y;
                ul[4*q+2] = aq.z + zq.z;
                ul[4*q+3] = aq.w + zq.w;
            }
            const int jrel = t_abs - j0;
            #pragma unroll
            for (int i = 0; i < PP; ++i) {
                const float val = (jrel == i) ? vint : ul[i];
                ul[i] = val;
                #pragma unroll
                for (int q = (i >> 2); q < 16; ++q) {
                    const float4 d = *(const float4*)&sm.m.diag[i][4 * q];
                    ul[4*q+0] = fmaf(d.x, val, ul[4*q+0]);
                    ul[4*q+1] = fmaf(d.y, val, ul[4*q+1]);
                    ul[4*q+2] = fmaf(d.z, val, ul[4*q+2]);
                    ul[4*q+3] = fmaf(d.w, val, ul[4*q+3]);
                }
            }
            #pragma unroll
            for (int q = 0; q < 16; ++q) {
                float4 v;
                v.x = ul[4*q+0]; v.y = ul[4*q+1]; v.z = ul[4*q+2]; v.w = ul[4*q+3];
                *(float4*)&sm.m.up[tid][4 * q] = v;
            }
        }
        __syncthreads();

        // ---- coalesced panel writeout (out doubles as u-scratch) ----
        {
            const int r0 = tid >> 4;          // 0..31
            const int c0 = (tid & 15) * 4;    // 0..60
            #pragma unroll
            for (int pass = 0; pass < 2; ++pass) {
                const int row = pass * 32 + r0;
                const float4 v = *(const float4*)&sm.m.up[row][c0];
                *(float4*)(out + (size_t)(b0 + row) * K_DIM + j0 + c0) = v;
            }
        }
        __syncthreads();   // global writes + smem reuse ordered before next panel
    }
}

extern "C" void kernel_launch(void* const* d_in, const int* in_sizes, int n_in,
                              void* d_out, int out_size) {
    const float* z     = (const float*)d_in[0];
    const int*   tgt   = (const int*)  d_in[1];
    const int*   vari  = (const int*)  d_in[2];
    const float* A     = (const float*)d_in[3];
    const float* means = (const float*)d_in[4];
    const float* logsc = (const float*)d_in[5];
    float* out = (float*)d_out;
    (void)in_sizes; (void)n_in; (void)out_size;

    scm_kernel<<<B_SZ / BT, NTH>>>(z, tgt, vari, A, means, logsc, out);
}

// round 7
// speedup vs baseline: 1.2481x; 1.2481x over previous
#include <cuda_runtime.h>
#include <cstdint>

#define B_SZ   8192
#define K_DIM  1024
#define V_N    2
#define BT     64      // batch rows per CTA
#define PP     64      // panel width
#define KC     32      // k-chunk
#define NTH    256     // 8 warps = 2 per SMSP
#define NPAN   (K_DIM / PP)
#define UR     (2*BT + 4)   // 132 floats, rows 16B-aligned
#define AR     (PP + 4)     // 68

// -------- packed f32x2 helpers (B300 FFMA2 path, PTX-only) --------
__device__ __forceinline__ unsigned long long pack2(float x) {
    unsigned long long r;
    unsigned int u = __float_as_uint(x);
    asm("mov.b64 %0, {%1, %1};" : "=l"(r) : "r"(u));
    return r;
}
__device__ __forceinline__ unsigned long long ffma2(unsigned long long a,
                                                    unsigned long long b,
                                                    unsigned long long c) {
    unsigned long long d;
    asm("fma.rn.f32x2 %0, %1, %2, %3;" : "=l"(d) : "l"(a), "l"(b), "l"(c));
    return d;
}

// GEMM-phase (double-buffered) and solve-phase smem alias (phases sync-separated)
union SMem {
    struct {
        float u_dup[2][KC][UR];   // u_dup[s][k][2b..2b+1] = u[b]
        float a_s[2][KC][AR];     // a_s[s][k][jj] = A[j0+jj][kb*KC+k]
    } g;                          // 51.2 KB
    struct {
        float diag[PP][AR];       // diag[i][jj] = A[j0+jj][j0+i], 0 unless i<jj
        float up[BT][AR];         // panel values
    } m;                          // 34.8 KB
};

__global__ void __launch_bounds__(NTH)
scm_kernel(const float* __restrict__ z,
           const int*   __restrict__ tgt,
           const int*   __restrict__ vari,
           const float* __restrict__ A,
           const float* __restrict__ means,
           const float* __restrict__ logsc,
           float*       __restrict__ out)
{
    __shared__ __align__(16) SMem sm;

    const int tid  = threadIdx.x;
    const int b0   = blockIdx.x * BT;
    const int lane = tid & 31;
    const int warp = tid >> 5;
    // warp-local tiling: each warp = 4 row-groups x 8 col-groups
    // -> per k: a-load 8x16B=128B (1 wavefront), u-loads 4x16B=64B (1 wf each)
    const int jg = (lane & 7) | ((warp & 1) << 3);    // 0..15 -> cols 4jg..4jg+3
    const int bg = (lane >> 3) | ((warp >> 1) << 2);  // 0..15 -> rows 4bg..4bg+3

    // ---- per-sample intervention scalar (threads 0..63) ----
    int   t_abs = -(1 << 30);
    float vint  = 0.0f;
    if (tid < BT) {
        const int b = b0 + tid;
        const int t = tgt[b];
        if (t >= 0) {
            const int v   = vari[b];
            const float m = means[t * V_N + v];
            const float s = expf(logsc[t * V_N + v]);
            vint  = fmaf(s, z[(size_t)b * K_DIM + t], m);
            t_abs = t;
        }
    }

    for (int p = 0; p < NPAN; ++p) {
        const int j0 = p * PP;

        // ===== GEMM: acc[r][pp] = sum_{k<j0} u[4bg+r][k] * A[j0+4jg+..][k] ====
        unsigned long long acc[4][2];
        #pragma unroll
        for (int i = 0; i < 4; ++i) { acc[i][0] = 0ULL; acc[i][1] = 0ULL; }

        const int nkb = 2 * p;
        if (nkb > 0) {
            float4 ru[2], ra[2];
            // stage chunk 0 into buffer 0
            #pragma unroll
            for (int q = 0; q < 2; ++q) {
                const int f = tid + NTH * q;
                const int r = f >> 3, c = f & 7;
                ru[q] = *(const float4*)(out + (size_t)(b0 + r) * K_DIM + 4 * c);
                ra[q] = *(const float4*)(A   + (size_t)(j0 + r) * K_DIM + 4 * c);
            }
            #pragma unroll
            for (int q = 0; q < 2; ++q) {
                const int f = tid + NTH * q;
                const int r = f >> 3, c = f & 7;
                const float uv[4] = {ru[q].x, ru[q].y, ru[q].z, ru[q].w};
                const float av[4] = {ra[q].x, ra[q].y, ra[q].z, ra[q].w};
                #pragma unroll
                for (int j = 0; j < 4; ++j) {
                    *(unsigned long long*)&sm.g.u_dup[0][4*c + j][2*r] = pack2(uv[j]);
                    sm.g.a_s[0][4*c + j][r] = av[j];
                }
            }
            __syncthreads();

            for (int kb = 0; kb < nkb; ++kb) {
                const bool more = (kb + 1 < nkb);
                if (more) {
                    #pragma unroll
                    for (int q = 0; q < 2; ++q) {
                        const int f = tid + NTH * q;
                        const int r = f >> 3, c = f & 7;
                        ru[q] = *(const float4*)(out + (size_t)(b0 + r) * K_DIM + (kb + 1) * KC + 4 * c);
                        ra[q] = *(const float4*)(A   + (size_t)(j0 + r) * K_DIM + (kb + 1) * KC + 4 * c);
                    }
                }
                const int s = kb & 1;
                const float* ub = &sm.g.u_dup[s][0][8 * bg];
                const float* ab = &sm.g.a_s[s][0][4 * jg];
                #pragma unroll 4
                for (int k = 0; k < KC; ++k) {
                    const ulonglong2 u01 = *(const ulonglong2*)(ub + k * UR);
                    const ulonglong2 u23 = *(const ulonglong2*)(ub + k * UR + 4);
                    const ulonglong2 bp  = *(const ulonglong2*)(ab + k * AR);
                    acc[0][0] = ffma2(u01.x, bp.x, acc[0][0]);
                    acc[0][1] = ffma2(u01.x, bp.y, acc[0][1]);
                    acc[1][0] = ffma2(u01.y, bp.x, acc[1][0]);
                    acc[1][1] = ffma2(u01.y, bp.y, acc[1][1]);
                    acc[2][0] = ffma2(u23.x, bp.x, acc[2][0]);
                    acc[2][1] = ffma2(u23.x, bp.y, acc[2][1]);
                    acc[3][0] = ffma2(u23.y, bp.x, acc[3][0]);
                    acc[3][1] = ffma2(u23.y, bp.y, acc[3][1]);
                }
                if (more) {
                    const int ns = s ^ 1;
                    #pragma unroll
                    for (int q = 0; q < 2; ++q) {
                        const int f = tid + NTH * q;
                        const int r = f >> 3, c = f & 7;
                        const float uv[4] = {ru[q].x, ru[q].y, ru[q].z, ru[q].w};
                        const float av[4] = {ra[q].x, ra[q].y, ra[q].z, ra[q].w};
                        #pragma unroll
                        for (int j = 0; j < 4; ++j) {
                            *(unsigned long long*)&sm.g.u_dup[ns][4*c + j][2*r] = pack2(uv[j]);
                            sm.g.a_s[ns][4*c + j][r] = av[j];
                        }
                    }
                }
                __syncthreads();
            }
        }

        // ========== switch to solve-phase smem (aliases GEMM tiles) ==========
        #pragma unroll
        for (int i = 0; i < 4; ++i) {
            *(unsigned long long*)&sm.m.up[4*bg + i][4*jg]     = acc[i][0];
            *(unsigned long long*)&sm.m.up[4*bg + i][4*jg + 2] = acc[i][1];
        }
        // diagonal block, transposed + strictly-lower masked
        {
            const int jj  = tid & 63;
            const int ig0 = (tid >> 6) * 16;
            const float* src = A + (size_t)(j0 + jj) * K_DIM + j0 + ig0;
            #pragma unroll
            for (int q = 0; q < 4; ++q) {
                const float4 r = *(const float4*)(src + 4 * q);
                const int i = ig0 + 4 * q;
                sm.m.diag[i + 0][jj] = (i + 0 < jj) ? r.x : 0.0f;
                sm.m.diag[i + 1][jj] = (i + 1 < jj) ? r.y : 0.0f;
                sm.m.diag[i + 2][jj] = (i + 2 < jj) ? r.z : 0.0f;
                sm.m.diag[i + 3][jj] = (i + 3 < jj) ? r.w : 0.0f;
            }
        }
        __syncthreads();

        // ======= in-panel sequential micro-solve: thread b owns a sample =====
        if (tid < BT) {
            float ul[PP];
            const float* zp = z + (size_t)(b0 + tid) * K_DIM + j0;
            #pragma unroll
            for (int q = 0; q < 16; ++q) {
                const float4 zq = *(const float4*)(zp + 4 * q);
                const float4 aq = *(const float4*)&sm.m.up[tid][4 * q];
                ul[4*q+0] = aq.x + zq.x;
                ul[4*q+1] = aq.y + zq.y;
                ul[4*q+2] = aq.z + zq.z;
                ul[4*q+3] = aq.w + zq.w;
            }
            const int jrel = t_abs - j0;
            #pragma unroll
            for (int i = 0; i < PP; ++i) {
                const float val = (jrel == i) ? vint : ul[i];
                ul[i] = val;
                #pragma unroll
                for (int q = (i >> 2); q < 16; ++q) {
                    const float4 d = *(const float4*)&sm.m.diag[i][4 * q];
                    ul[4*q+0] = fmaf(d.x, val, ul[4*q+0]);
                    ul[4*q+1] = fmaf(d.y, val, ul[4*q+1]);
                    ul[4*q+2] = fmaf(d.z, val, ul[4*q+2]);
                    ul[4*q+3] = fmaf(d.w, val, ul[4*q+3]);
                }
            }
            #pragma unroll
            for (int q = 0; q < 16; ++q) {
                float4 v;
                v.x = ul[4*q+0]; v.y = ul[4*q+1]; v.z = ul[4*q+2]; v.w = ul[4*q+3];
                *(float4*)&sm.m.up[tid][4 * q] = v;
            }
        }
        __syncthreads();

        // ---- coalesced panel writeout (out doubles as u-scratch) ----
        {
            const int r0 = tid >> 4;          // 0..15
            const int c0 = (tid & 15) * 4;    // 0..60
            #pragma unroll
            for (int pass = 0; pass < 4; ++pass) {
                const int row = pass * 16 + r0;
                const float4 v = *(const float4*)&sm.m.up[row][c0];
                *(float4*)(out + (size_t)(b0 + row) * K_DIM + j0 + c0) = v;
            }
        }
        __syncthreads();
    }
}

extern "C" void kernel_launch(void* const* d_in, const int* in_sizes, int n_in,
                              void* d_out, int out_size) {
    const float* z     = (const float*)d_in[0];
    const int*   tgt   = (const int*)  d_in[1];
    const int*   vari  = (const int*)  d_in[2];
    const float* A     = (const float*)d_in[3];
    const float* means = (const float*)d_in[4];
    const float* logsc = (const float*)d_in[5];
    float* out = (float*)d_out;
    (void)in_sizes; (void)n_in; (void)out_size;

    scm_kernel<<<B_SZ / BT, NTH>>>(z, tgt, vari, A, means, logsc, out);
}